// round 15
// baseline (speedup 1.0000x reference)
#include <cuda_runtime.h>
#include <cuda_fp16.h>
#include <cstdint>

#define B_  64
#define N_  2048
#define I_  16
#define JK_ 1024

typedef unsigned long long ull;

// Scratch: u_hat fp16 [b][n][jk] (256 MB); three s buffers (iter 0,1,2)
__device__ __half g_uhat[(size_t)B_ * N_ * JK_];
__device__ float  g_sb[3][B_ * JK_];

// ---------------- packed fp32x2 helpers (sm_100+) ----------------
static __device__ __forceinline__ ull fma2(ull a, ull b, ull c) {
    ull d;
    asm("fma.rn.f32x2 %0, %1, %2, %3;" : "=l"(d) : "l"(a), "l"(b), "l"(c));
    return d;
}
static __device__ __forceinline__ float2 ull2f2(ull v) {
    float2 f;
    asm("mov.b64 {%0, %1}, %2;" : "=f"(f.x), "=f"(f.y) : "l"(v));
    return f;
}
static __device__ __forceinline__ ull packf2(float x, float y) {
    ull r;
    asm("mov.b64 %0, {%1, %2};" : "=l"(r) : "f"(x), "f"(y));
    return r;
}
static __device__ __forceinline__ ull dupf(float x) {
    ull r;
    asm("mov.b64 %0, {%1, %1};" : "=l"(r) : "f"(x));
    return r;
}
static __device__ __forceinline__ ull h2f2(unsigned int h) {
    __half2 hh = *reinterpret_cast<__half2*>(&h);
    float2 f = __half22float2(hh);
    return packf2(f.x, f.y);
}
static __device__ __forceinline__ void red4(float* p, float4 v) {
    asm volatile("red.global.add.v4.f32 [%0], {%1,%2,%3,%4};"
                 :: "l"(p), "f"(v.x), "f"(v.y), "f"(v.z), "f"(v.w) : "memory");
}
static __device__ __forceinline__ void redf(float* p, float v) {
    asm volatile("red.global.add.f32 [%0], %1;" :: "l"(p), "f"(v) : "memory");
}
static __device__ __forceinline__ uint32_t smem_u32(const void* p) {
    uint32_t a;
    asm("{ .reg .u64 t; cvta.to.shared.u64 t, %1; cvt.u32.u64 %0, t; }"
        : "=r"(a) : "l"(p));
    return a;
}
static __device__ __forceinline__ void cp_async16(uint32_t saddr, const void* gaddr) {
    asm volatile("cp.async.cg.shared.global [%0], [%1], 16;"
                 :: "r"(saddr), "l"(gaddr) : "memory");
}
static __device__ __forceinline__ void cp_commit() {
    asm volatile("cp.async.commit_group;" ::: "memory");
}
template <int N>
static __device__ __forceinline__ void cp_wait() {
    asm volatile("cp.async.wait_group %0;" :: "n"(N) : "memory");
}
// Ampere-class HMMA: m16n8k16, f16 in / f32 accum (baseline PTX, compute_103-safe)
static __device__ __forceinline__ void mma16816(float* d,
                                                uint32_t a0, uint32_t a1,
                                                uint32_t a2, uint32_t a3,
                                                uint32_t b0, uint32_t b1) {
    asm("mma.sync.aligned.m16n8k16.row.col.f32.f16.f16.f32 "
        "{%0,%1,%2,%3}, {%4,%5,%6,%7}, {%8,%9}, {%10,%11,%12,%13};"
        : "=f"(d[0]), "=f"(d[1]), "=f"(d[2]), "=f"(d[3])
        : "r"(a0), "r"(a1), "r"(a2), "r"(a3), "r"(b0), "r"(b1),
          "f"(0.0f), "f"(0.0f), "f"(0.0f), "f"(0.0f));
}
static __device__ __forceinline__ unsigned int f2h2(float x, float y) {
    __half2 h = __floats2half2_rn(x, y);
    return *reinterpret_cast<unsigned int*>(&h);
}

__global__ void __launch_bounds__(1024) k_init() {
    int idx = blockIdx.x * 1024 + threadIdx.x;   // grid 192 -> 196608
    (&g_sb[0][0])[idx] = 0.0f;
}

// ---------------- HMMA u_hat generation + s0 (direct fragment stores) ------
// Grid 1184 = 148 n-strips x 8 jk-eighths, 256 thr, 2 CTAs/SM.
// Per n: D[b 64, jk 128] = X[b,i] * W[jk,i]^T via 64 HMMA m16n8k16.
// u_hat stored DIRECTLY from C fragments (half2 STG; adjacent j8 fill
// adjacent 16B so L1 merges sectors). One __syncthreads per n. s0 in regs.
#define TS 24     // staged tile row stride (halfs); bank-conflict-free frags
__global__ void __launch_bounds__(256, 2) k_uhat(const float* __restrict__ inp,
                                                 const float* __restrict__ W) {
    __shared__ __half Wt[2][128 * TS];   // [buf][jk][i]  2x6KB
    __shared__ __half Xt[2][64 * TS];    // [buf][b][i]   2x3KB

    const int tid = threadIdx.x;
    const int w = tid >> 5, l = tid & 31;
    const int g = l >> 2, t = l & 3;     // fragment group / thread-in-group
    const int jkQ = blockIdx.x & 7;      // jk eighth (128 jk)
    const int idx = blockIdx.x >> 3;     // n-strip 0..147

    // staging sources
    const int wr_ = tid >> 1;            // W row to stage (0..127)
    const int wi  = (tid & 1) * 8;       // i half
    const int jkg = jkQ * 128 + wr_;
    const float* wsrc = W + ((size_t)(jkg >> 5) * N_) * 512
                        + (size_t)(jkg & 31) * 16 + wi;
    const int xb = tid >> 2, xi4 = (tid & 3) * 4;
    const float* xsrc = inp + (size_t)xb * N_ * 16 + xi4;

    const int total = (N_ - idx + 147) / 148;

    float4 wv0, wv1, xv;
    {   // prologue: stage n0 into buffer 0
        const float* ws = wsrc + (size_t)idx * 512;
        wv0 = *reinterpret_cast<const float4*>(ws);
        wv1 = *reinterpret_cast<const float4*>(ws + 4);
        xv  = *reinterpret_cast<const float4*>(xsrc + (size_t)idx * 16);
        uint4 v;
        v.x = f2h2(wv0.x, wv0.y); v.y = f2h2(wv0.z, wv0.w);
        v.z = f2h2(wv1.x, wv1.y); v.w = f2h2(wv1.z, wv1.w);
        *reinterpret_cast<uint4*>(Wt[0] + wr_ * TS + wi) = v;
        uint2 xu;
        xu.x = f2h2(xv.x, xv.y); xu.y = f2h2(xv.z, xv.w);
        *reinterpret_cast<uint2*>(Xt[0] + xb * TS + xi4) = xu;
    }

    float s0r[8][4];
    #pragma unroll
    for (int j = 0; j < 8; j++)
        #pragma unroll
        for (int k = 0; k < 4; k++) s0r[j][k] = 0.0f;

    const int btile = w & 3;             // warp's b tile (16 b)
    const int jhalf = w >> 2;            // warp's jk half (64 jk)
    const int arow  = btile * 16 + g;

    // fragment-direct u_hat store bases (row arow and arow+8), jk part fixed
    const int jkbase = jkQ * 128 + jhalf * 64 + 2 * t;
    __half* ub0 = g_uhat + (size_t)arow * N_ * JK_ + jkbase;
    __half* ub1 = g_uhat + (size_t)(arow + 8) * N_ * JK_ + jkbase;

    for (int it = 0; it < total; it++) {
        __syncthreads();
        const int n = idx + it * 148;
        const bool more = (it + 1 < total);
        if (more) {
            const int nn = n + 148;
            const float* ws = wsrc + (size_t)nn * 512;
            wv0 = *reinterpret_cast<const float4*>(ws);
            wv1 = *reinterpret_cast<const float4*>(ws + 4);
            xv  = *reinterpret_cast<const float4*>(xsrc + (size_t)nn * 16);
        }
        const __half* Wc = Wt[it & 1];
        const __half* Xc = Xt[it & 1];

        // A fragments (X): rows arow, arow+8; k pairs 2t, 2t+8
        uint32_t ra0 = *reinterpret_cast<const uint32_t*>(Xc + arow * TS + 2 * t);
        uint32_t ra1 = *reinterpret_cast<const uint32_t*>(Xc + (arow + 8) * TS + 2 * t);
        uint32_t ra2 = *reinterpret_cast<const uint32_t*>(Xc + arow * TS + 2 * t + 8);
        uint32_t ra3 = *reinterpret_cast<const uint32_t*>(Xc + (arow + 8) * TS + 2 * t + 8);

        float acc[8][4];
        #pragma unroll
        for (int j8 = 0; j8 < 8; j8++) {
            const int brow = jhalf * 64 + j8 * 8 + g;
            uint32_t rb0 = *reinterpret_cast<const uint32_t*>(Wc + brow * TS + 2 * t);
            uint32_t rb1 = *reinterpret_cast<const uint32_t*>(Wc + brow * TS + 2 * t + 8);
            mma16816(acc[j8], ra0, ra1, ra2, ra3, rb0, rb1);
        }

        if (more) {   // stage next n into other buffer
            const int nb = (it + 1) & 1;
            uint4 v;
            v.x = f2h2(wv0.x, wv0.y); v.y = f2h2(wv0.z, wv0.w);
            v.z = f2h2(wv1.x, wv1.y); v.w = f2h2(wv1.z, wv1.w);
            *reinterpret_cast<uint4*>(Wt[nb] + wr_ * TS + wi) = v;
            uint2 xu;
            xu.x = f2h2(xv.x, xv.y); xu.y = f2h2(xv.z, xv.w);
            *reinterpret_cast<uint2*>(Xt[nb] + xb * TS + xi4) = xu;
        }

        // s0 += acc; u_hat stored straight from fragments (half2 STG)
        __half* u0 = ub0 + (size_t)n * JK_;
        __half* u1 = ub1 + (size_t)n * JK_;
        #pragma unroll
        for (int j8 = 0; j8 < 8; j8++) {
            s0r[j8][0] += acc[j8][0]; s0r[j8][1] += acc[j8][1];
            s0r[j8][2] += acc[j8][2]; s0r[j8][3] += acc[j8][3];
            *reinterpret_cast<__half2*>(u0 + j8 * 8) =
                __floats2half2_rn(acc[j8][0], acc[j8][1]);
            *reinterpret_cast<__half2*>(u1 + j8 * 8) =
                __floats2half2_rn(acc[j8][2], acc[j8][3]);
        }
    }

    // flush s0 (x 1/32): fragment-layout scalar reductions (one-time)
    #pragma unroll
    for (int j8 = 0; j8 < 8; j8++) {
        const int jk = jkQ * 128 + jhalf * 64 + j8 * 8 + 2 * t;
        float* p0 = &g_sb[0][(size_t)arow * JK_ + jk];
        float* p1 = &g_sb[0][(size_t)(arow + 8) * JK_ + jk];
        redf(p0,     s0r[j8][0] * 0.03125f);
        redf(p0 + 1, s0r[j8][1] * 0.03125f);
        redf(p1,     s0r[j8][2] * 0.03125f);
        redf(p1 + 1, s0r[j8][3] * 0.03125f);
    }
}

// ---------------- fused squash + routing pass (R12, measured 72.2us) -------
__global__ void __launch_bounds__(256, 2)
k_route(int ia, int ib, int io, int two) {
    extern __shared__ float smr[];
    float* V_sm = smr;            // 1024 floats
    float* ws   = smr + 1024;     // 8192 floats
    float* ring = smr + 9216;     // 16384 floats

    const float* sa = g_sb[ia];
    const float* sb = g_sb[ib];
    float* sout = g_sb[io];

    const int chunk = blockIdx.x;      // 0..31
    const int b     = blockIdx.y;      // 0..63
    const int tid   = threadIdx.x;     // 256
    const int warp  = tid >> 5;
    const int lane  = tid & 31;

    #pragma unroll
    for (int r = 0; r < 4; r++) {
        int j = warp * 4 + r;
        float va = sa[b * JK_ + j * 32 + lane];
        float sq = va * va;
        #pragma unroll
        for (int o = 16; o; o >>= 1) sq += __shfl_xor_sync(0xffffffffu, sq, o);
        float val = (sq / ((1.0f + sq) * sqrtf(sq + 1e-7f))) * va;
        if (two) {
            float vb = sb[b * JK_ + j * 32 + lane];
            float sqb = vb * vb;
            #pragma unroll
            for (int o = 16; o; o >>= 1) sqb += __shfl_xor_sync(0xffffffffu, sqb, o);
            val += (sqb / ((1.0f + sqb) * sqrtf(sqb + 1e-7f))) * vb;
        }
        V_sm[j * 32 + lane] = val;
    }
    __syncthreads();

    ull vq[4][4];
    #pragma unroll
    for (int q = 0; q < 4; q++) {
        float4 a = *reinterpret_cast<const float4*>(V_sm + q * 256 + lane * 8);
        float4 c = *reinterpret_cast<const float4*>(V_sm + q * 256 + lane * 8 + 4);
        vq[q][0] = packf2(a.x, a.y); vq[q][1] = packf2(a.z, a.w);
        vq[q][2] = packf2(c.x, c.y); vq[q][3] = packf2(c.z, c.w);
    }

    ull sacc[4][4];
    #pragma unroll
    for (int q = 0; q < 4; q++)
        #pragma unroll
        for (int m = 0; m < 4; m++) sacc[q][m] = 0ull;

    const char* row0 = reinterpret_cast<const char*>(
        g_uhat + ((size_t)b * N_ + (size_t)(chunk * 64 + warp * 8)) * JK_) + lane * 16;
    const uint32_t rbase = smem_u32(ring) + warp * 8192 + lane * 16;

    #pragma unroll
    for (int r = 0; r < 4; r++) {
        #pragma unroll
        for (int q = 0; q < 4; q++)
            cp_async16(rbase + r * 2048 + q * 512, row0 + (size_t)r * 2048 + q * 512);
        cp_commit();
    }

    #pragma unroll
    for (int r = 0; r < 8; r++) {
        if (r <= 4)      cp_wait<3>();
        else if (r == 5) cp_wait<2>();
        else if (r == 6) cp_wait<1>();
        else             cp_wait<0>();

        const float* slot = ring + (size_t)(warp * 2048 + (r & 3) * 512) + lane * 4;
        uint4 c4[4];
        #pragma unroll
        for (int q = 0; q < 4; q++)
            c4[q] = *reinterpret_cast<const uint4*>(slot + q * 128);

        if (r < 4) {
            #pragma unroll
            for (int q = 0; q < 4; q++)
                cp_async16(rbase + (r & 3) * 2048 + q * 512,
                           row0 + (size_t)(r + 4) * 2048 + q * 512);
            cp_commit();
        }

        float e[4];
        #pragma unroll
        for (int q = 0; q < 4; q++) {
            ull u0 = h2f2(c4[q].x), u1 = h2f2(c4[q].y);
            ull u2 = h2f2(c4[q].z), u3 = h2f2(c4[q].w);
            ull d = fma2(u0, vq[q][0], fma2(u1, vq[q][1],
                    fma2(u2, vq[q][2], fma2(u3, vq[q][3], 0ull))));
            float2 df = ull2f2(d);
            float bp = df.x + df.y;
            bp += __shfl_xor_sync(0xffffffffu, bp, 1);
            bp += __shfl_xor_sync(0xffffffffu, bp, 2);
            e[q] = __expf(bp);
        }
        float tot = e[0] + e[1] + e[2] + e[3];
        tot += __shfl_xor_sync(0xffffffffu, tot, 4);
        tot += __shfl_xor_sync(0xffffffffu, tot, 8);
        tot += __shfl_xor_sync(0xffffffffu, tot, 16);
        float inv = __fdividef(1.0f, tot);
        #pragma unroll
        for (int q = 0; q < 4; q++) {
            ull cq2 = dupf(e[q] * inv);
            ull u0 = h2f2(c4[q].x), u1 = h2f2(c4[q].y);
            ull u2 = h2f2(c4[q].z), u3 = h2f2(c4[q].w);
            sacc[q][0] = fma2(cq2, u0, sacc[q][0]);
            sacc[q][1] = fma2(cq2, u1, sacc[q][1]);
            sacc[q][2] = fma2(cq2, u2, sacc[q][2]);
            sacc[q][3] = fma2(cq2, u3, sacc[q][3]);
        }
    }

    #pragma unroll
    for (int q = 0; q < 4; q++) {
        float2 f0 = ull2f2(sacc[q][0]), f1 = ull2f2(sacc[q][1]);
        float2 f2 = ull2f2(sacc[q][2]), f3 = ull2f2(sacc[q][3]);
        float* wp = ws + warp * 1024 + q * 256 + lane * 8;
        *reinterpret_cast<float4*>(wp)     = make_float4(f0.x, f0.y, f1.x, f1.y);
        *reinterpret_cast<float4*>(wp + 4) = make_float4(f2.x, f2.y, f3.x, f3.y);
    }
    __syncthreads();

    float4 a = *reinterpret_cast<const float4*>(ws + tid * 4);
    #pragma unroll
    for (int w2 = 1; w2 < 8; w2++) {
        float4 x = *reinterpret_cast<const float4*>(ws + w2 * 1024 + tid * 4);
        a.x += x.x; a.y += x.y; a.z += x.z; a.w += x.w;
    }
    red4(sout + b * JK_ + tid * 4, a);
}

// ---------------- final squash ----------------
__global__ void __launch_bounds__(1024) k_squash_final(float* __restrict__ out) {
    const int b   = blockIdx.x;
    const int tid = threadIdx.x;
    float sv = g_sb[2][b * JK_ + tid];
    float sq = sv * sv;
    #pragma unroll
    for (int o = 16; o; o >>= 1) sq += __shfl_xor_sync(0xffffffffu, sq, o);
    out[b * JK_ + tid] = (sq / ((1.0f + sq) * sqrtf(sq + 1e-7f))) * sv;
}

extern "C" void kernel_launch(void* const* d_in, const int* in_sizes, int n_in,
                              void* d_out, int out_size) {
    const float* inp = (const float*)d_in[0];   // [64, 2048, 16]
    const float* W   = (const float*)d_in[1];   // [32, 2048, 32, 16]
    float* out = (float*)d_out;                 // [64, 32, 32]

    cudaFuncSetAttribute(k_route, cudaFuncAttributeMaxDynamicSharedMemorySize, 102400);

    k_init<<<192, 1024>>>();                            // zero s0,s1,s2
    k_uhat<<<1184, 256>>>(inp, W);                      // HMMA u_hat + s0 (direct STG)
    k_route<<<dim3(32, 64), 256, 102400>>>(0, 0, 1, 0); // V0 -> s1
    k_route<<<dim3(32, 64), 256, 102400>>>(0, 1, 2, 1); // V0+V1 -> s2
    k_squash_final<<<64, 1024>>>(out);
}

// round 16
// speedup vs baseline: 1.9999x; 1.9999x over previous
#include <cuda_runtime.h>
#include <cuda_fp16.h>
#include <cstdint>

#define B_  64
#define N_  2048
#define I_  16
#define JK_ 1024

typedef unsigned long long ull;

// Scratch: u_hat fp16 [b][n][jk] (256 MB); three s buffers (iter 0,1,2)
__device__ __half g_uhat[(size_t)B_ * N_ * JK_];
__device__ float  g_sb[3][B_ * JK_];

// ---------------- packed fp32x2 helpers (sm_100+) ----------------
static __device__ __forceinline__ ull fma2(ull a, ull b, ull c) {
    ull d;
    asm("fma.rn.f32x2 %0, %1, %2, %3;" : "=l"(d) : "l"(a), "l"(b), "l"(c));
    return d;
}
static __device__ __forceinline__ float2 ull2f2(ull v) {
    float2 f;
    asm("mov.b64 {%0, %1}, %2;" : "=f"(f.x), "=f"(f.y) : "l"(v));
    return f;
}
static __device__ __forceinline__ ull packf2(float x, float y) {
    ull r;
    asm("mov.b64 %0, {%1, %2};" : "=l"(r) : "f"(x), "f"(y));
    return r;
}
static __device__ __forceinline__ ull dupf(float x) {
    ull r;
    asm("mov.b64 %0, {%1, %1};" : "=l"(r) : "f"(x));
    return r;
}
static __device__ __forceinline__ ull h2f2(unsigned int h) {
    __half2 hh = *reinterpret_cast<__half2*>(&h);
    float2 f = __half22float2(hh);
    return packf2(f.x, f.y);
}
static __device__ __forceinline__ void red4(float* p, float4 v) {
    asm volatile("red.global.add.v4.f32 [%0], {%1,%2,%3,%4};"
                 :: "l"(p), "f"(v.x), "f"(v.y), "f"(v.z), "f"(v.w) : "memory");
}
static __device__ __forceinline__ void redf(float* p, float v) {
    asm volatile("red.global.add.f32 [%0], %1;" :: "l"(p), "f"(v) : "memory");
}
static __device__ __forceinline__ uint32_t smem_u32(const void* p) {
    uint32_t a;
    asm("{ .reg .u64 t; cvta.to.shared.u64 t, %1; cvt.u32.u64 %0, t; }"
        : "=r"(a) : "l"(p));
    return a;
}
static __device__ __forceinline__ void cp_async16(uint32_t saddr, const void* gaddr) {
    asm volatile("cp.async.cg.shared.global [%0], [%1], 16;"
                 :: "r"(saddr), "l"(gaddr) : "memory");
}
static __device__ __forceinline__ void cp_commit() {
    asm volatile("cp.async.commit_group;" ::: "memory");
}
template <int N>
static __device__ __forceinline__ void cp_wait() {
    asm volatile("cp.async.wait_group %0;" :: "n"(N) : "memory");
}
// Ampere-class HMMA: m16n8k16, f16 in / f32 accum (baseline PTX, compute_103-safe)
static __device__ __forceinline__ void mma16816(float* d,
                                                uint32_t a0, uint32_t a1,
                                                uint32_t a2, uint32_t a3,
                                                uint32_t b0, uint32_t b1) {
    asm("mma.sync.aligned.m16n8k16.row.col.f32.f16.f16.f32 "
        "{%0,%1,%2,%3}, {%4,%5,%6,%7}, {%8,%9}, {%10,%11,%12,%13};"
        : "=f"(d[0]), "=f"(d[1]), "=f"(d[2]), "=f"(d[3])
        : "r"(a0), "r"(a1), "r"(a2), "r"(a3), "r"(b0), "r"(b1),
          "f"(0.0f), "f"(0.0f), "f"(0.0f), "f"(0.0f));
}
static __device__ __forceinline__ unsigned int f2h2(float x, float y) {
    __half2 h = __floats2half2_rn(x, y);
    return *reinterpret_cast<unsigned int*>(&h);
}

__global__ void __launch_bounds__(1024) k_init() {
    int idx = blockIdx.x * 1024 + threadIdx.x;   // grid 192 -> 196608
    (&g_sb[0][0])[idx] = 0.0f;
}

// ---------------- HMMA u_hat generation + s0 (paired n, bounce tile) -------
// Grid 1184 = 148 n-strips x 8 jk-eighths, 256 thr, 2 CTAs/SM.
// Processes TWO n per barrier phase: one __syncthreads per n instead of two,
// doubled staging prefetch distance. D goes through a padded smem bounce tile
// (per-n) for coalesced 16B u_hat stores. s0 accumulated in frag registers.
#define TS 24     // staged tile row stride (halfs)
#define DS 136    // D bounce tile row stride (halfs)
__global__ void __launch_bounds__(256, 2) k_uhat(const float* __restrict__ inp,
                                                 const float* __restrict__ W) {
    extern __shared__ __half sh[];
    __half* Wt  = sh;            // [buf][s][128*TS]  24.0 KB
    __half* Xt  = sh + 12288;    // [buf][s][64*TS]   12.0 KB
    __half* Dsm = sh + 18432;    // [s][64*DS]        34.8 KB

    const int tid = threadIdx.x;
    const int w = tid >> 5, l = tid & 31;
    const int g = l >> 2, t = l & 3;
    const int jkQ = blockIdx.x & 7;
    const int idx = blockIdx.x >> 3;

    // staging sources (per n)
    const int wr_ = tid >> 1;            // W row to stage (0..127)
    const int wi  = (tid & 1) * 8;       // i half
    const int jkg = jkQ * 128 + wr_;
    const float* wsrc = W + ((size_t)(jkg >> 5) * N_) * 512
                        + (size_t)(jkg & 31) * 16 + wi;
    const int xb = tid >> 2, xi4 = (tid & 3) * 4;
    const float* xsrc = inp + (size_t)xb * N_ * 16 + xi4;

    const int total  = (N_ - idx + 147) / 148;
    const int nPairs = (total + 1) >> 1;

    float4 wA0, wA1, xA, wB0, wB1, xB;
    {   // prologue: load+stage pair 0 into buf 0
        int n1 = idx + 148; int n1c = n1 < N_ ? n1 : idx;
        const float* wsA = wsrc + (size_t)idx * 512;
        const float* wsB = wsrc + (size_t)n1c * 512;
        wA0 = *reinterpret_cast<const float4*>(wsA);
        wA1 = *reinterpret_cast<const float4*>(wsA + 4);
        xA  = *reinterpret_cast<const float4*>(xsrc + (size_t)idx * 16);
        wB0 = *reinterpret_cast<const float4*>(wsB);
        wB1 = *reinterpret_cast<const float4*>(wsB + 4);
        xB  = *reinterpret_cast<const float4*>(xsrc + (size_t)n1c * 16);
        #pragma unroll
        for (int s = 0; s < 2; s++) {
            float4 w0 = s ? wB0 : wA0, w1 = s ? wB1 : wA1, xv = s ? xB : xA;
            uint4 v;
            v.x = f2h2(w0.x, w0.y); v.y = f2h2(w0.z, w0.w);
            v.z = f2h2(w1.x, w1.y); v.w = f2h2(w1.z, w1.w);
            *reinterpret_cast<uint4*>(Wt + s * (128 * TS) + wr_ * TS + wi) = v;
            uint2 xu;
            xu.x = f2h2(xv.x, xv.y); xu.y = f2h2(xv.z, xv.w);
            *reinterpret_cast<uint2*>(Xt + s * (64 * TS) + xb * TS + xi4) = xu;
        }
    }

    float s0r[8][4];
    #pragma unroll
    for (int j = 0; j < 8; j++)
        #pragma unroll
        for (int k = 0; k < 4; k++) s0r[j][k] = 0.0f;

    const int btile = w & 3;             // warp's b tile (16 b)
    const int jhalf = w >> 2;            // warp's jk half (64 jk)
    const int arow  = btile * 16 + g;

    for (int pt = 0; pt < nPairs; pt++) {
        __syncthreads();
        const bool more = (pt + 1 < nPairs);
        if (more) {   // prefetch pair pt+1
            int n0 = idx + (2 * pt + 2) * 148;
            int n1 = n0 + 148;
            int n0c = n0 < N_ ? n0 : idx;
            int n1c = n1 < N_ ? n1 : idx;
            const float* wsA = wsrc + (size_t)n0c * 512;
            const float* wsB = wsrc + (size_t)n1c * 512;
            wA0 = *reinterpret_cast<const float4*>(wsA);
            wA1 = *reinterpret_cast<const float4*>(wsA + 4);
            xA  = *reinterpret_cast<const float4*>(xsrc + (size_t)n0c * 16);
            wB0 = *reinterpret_cast<const float4*>(wsB);
            wB1 = *reinterpret_cast<const float4*>(wsB + 4);
            xB  = *reinterpret_cast<const float4*>(xsrc + (size_t)n1c * 16);
        }
        const int buf = pt & 1;

        // ---- compute both n of the pair ----
        #pragma unroll
        for (int s = 0; s < 2; s++) {
            const int n = idx + (2 * pt + s) * 148;
            if (n >= N_) break;
            const __half* Wc = Wt + (buf * 2 + s) * (128 * TS);
            const __half* Xc = Xt + (buf * 2 + s) * (64 * TS);

            uint32_t ra0 = *reinterpret_cast<const uint32_t*>(Xc + arow * TS + 2 * t);
            uint32_t ra1 = *reinterpret_cast<const uint32_t*>(Xc + (arow + 8) * TS + 2 * t);
            uint32_t ra2 = *reinterpret_cast<const uint32_t*>(Xc + arow * TS + 2 * t + 8);
            uint32_t ra3 = *reinterpret_cast<const uint32_t*>(Xc + (arow + 8) * TS + 2 * t + 8);

            float acc[8][4];
            #pragma unroll
            for (int j8 = 0; j8 < 8; j8++) {
                const int brow = jhalf * 64 + j8 * 8 + g;
                uint32_t rb0 = *reinterpret_cast<const uint32_t*>(Wc + brow * TS + 2 * t);
                uint32_t rb1 = *reinterpret_cast<const uint32_t*>(Wc + brow * TS + 2 * t + 8);
                mma16816(acc[j8], ra0, ra1, ra2, ra3, rb0, rb1);
            }
            // s0 += acc; bounce store (conflict-free half2)
            __half* Ds = Dsm + s * (64 * DS);
            #pragma unroll
            for (int j8 = 0; j8 < 8; j8++) {
                s0r[j8][0] += acc[j8][0]; s0r[j8][1] += acc[j8][1];
                s0r[j8][2] += acc[j8][2]; s0r[j8][3] += acc[j8][3];
                const int jkl = jhalf * 64 + j8 * 8 + 2 * t;
                *reinterpret_cast<__half2*>(Ds + arow * DS + jkl) =
                    __floats2half2_rn(acc[j8][0], acc[j8][1]);
                *reinterpret_cast<__half2*>(Ds + (arow + 8) * DS + jkl) =
                    __floats2half2_rn(acc[j8][2], acc[j8][3]);
            }
        }

        if (more) {   // stage prefetched pair into other buffer
            const int nb = buf ^ 1;
            #pragma unroll
            for (int s = 0; s < 2; s++) {
                float4 w0 = s ? wB0 : wA0, w1 = s ? wB1 : wA1, xv = s ? xB : xA;
                uint4 v;
                v.x = f2h2(w0.x, w0.y); v.y = f2h2(w0.z, w0.w);
                v.z = f2h2(w1.x, w1.y); v.w = f2h2(w1.z, w1.w);
                *reinterpret_cast<uint4*>(Wt + (nb * 2 + s) * (128 * TS) + wr_ * TS + wi) = v;
                uint2 xu;
                xu.x = f2h2(xv.x, xv.y); xu.y = f2h2(xv.z, xv.w);
                *reinterpret_cast<uint2*>(Xt + (nb * 2 + s) * (64 * TS) + xb * TS + xi4) = xu;
            }
        }
        __syncthreads();

        // ---- epilogue: coalesced u_hat stores for both n ----
        #pragma unroll
        for (int s = 0; s < 2; s++) {
            const int n = idx + (2 * pt + s) * 148;
            if (n >= N_) break;
            const __half* sp = Dsm + s * (64 * DS) + (tid >> 2) * DS + (tid & 3) * 32;
            __half* up = g_uhat + ((size_t)(tid >> 2) * N_ + n) * JK_
                         + jkQ * 128 + (tid & 3) * 32;
            #pragma unroll
            for (int k = 0; k < 4; k++)
                reinterpret_cast<uint4*>(up)[k] =
                    reinterpret_cast<const uint4*>(sp)[k];
        }
    }

    // flush s0 (x 1/32): fragment-layout scalar reductions (one-time)
    #pragma unroll
    for (int j8 = 0; j8 < 8; j8++) {
        const int jk = jkQ * 128 + jhalf * 64 + j8 * 8 + 2 * t;
        float* p0 = &g_sb[0][(size_t)arow * JK_ + jk];
        float* p1 = &g_sb[0][(size_t)(arow + 8) * JK_ + jk];
        redf(p0,     s0r[j8][0] * 0.03125f);
        redf(p0 + 1, s0r[j8][1] * 0.03125f);
        redf(p1,     s0r[j8][2] * 0.03125f);
        redf(p1 + 1, s0r[j8][3] * 0.03125f);
    }
}

// ---------------- fused squash + routing pass (R12, measured 72.2us) -------
__global__ void __launch_bounds__(256, 2)
k_route(int ia, int ib, int io, int two) {
    extern __shared__ float smr[];
    float* V_sm = smr;            // 1024 floats
    float* ws   = smr + 1024;     // 8192 floats
    float* ring = smr + 9216;     // 16384 floats

    const float* sa = g_sb[ia];
    const float* sb = g_sb[ib];
    float* sout = g_sb[io];

    const int chunk = blockIdx.x;      // 0..31
    const int b     = blockIdx.y;      // 0..63
    const int tid   = threadIdx.x;     // 256
    const int warp  = tid >> 5;
    const int lane  = tid & 31;

    #pragma unroll
    for (int r = 0; r < 4; r++) {
        int j = warp * 4 + r;
        float va = sa[b * JK_ + j * 32 + lane];
        float sq = va * va;
        #pragma unroll
        for (int o = 16; o; o >>= 1) sq += __shfl_xor_sync(0xffffffffu, sq, o);
        float val = (sq / ((1.0f + sq) * sqrtf(sq + 1e-7f))) * va;
        if (two) {
            float vb = sb[b * JK_ + j * 32 + lane];
            float sqb = vb * vb;
            #pragma unroll
            for (int o = 16; o; o >>= 1) sqb += __shfl_xor_sync(0xffffffffu, sqb, o);
            val += (sqb / ((1.0f + sqb) * sqrtf(sqb + 1e-7f))) * vb;
        }
        V_sm[j * 32 + lane] = val;
    }
    __syncthreads();

    ull vq[4][4];
    #pragma unroll
    for (int q = 0; q < 4; q++) {
        float4 a = *reinterpret_cast<const float4*>(V_sm + q * 256 + lane * 8);
        float4 c = *reinterpret_cast<const float4*>(V_sm + q * 256 + lane * 8 + 4);
        vq[q][0] = packf2(a.x, a.y); vq[q][1] = packf2(a.z, a.w);
        vq[q][2] = packf2(c.x, c.y); vq[q][3] = packf2(c.z, c.w);
    }

    ull sacc[4][4];
    #pragma unroll
    for (int q = 0; q < 4; q++)
        #pragma unroll
        for (int m = 0; m < 4; m++) sacc[q][m] = 0ull;

    const char* row0 = reinterpret_cast<const char*>(
        g_uhat + ((size_t)b * N_ + (size_t)(chunk * 64 + warp * 8)) * JK_) + lane * 16;
    const uint32_t rbase = smem_u32(ring) + warp * 8192 + lane * 16;

    #pragma unroll
    for (int r = 0; r < 4; r++) {
        #pragma unroll
        for (int q = 0; q < 4; q++)
            cp_async16(rbase + r * 2048 + q * 512, row0 + (size_t)r * 2048 + q * 512);
        cp_commit();
    }

    #pragma unroll
    for (int r = 0; r < 8; r++) {
        if (r <= 4)      cp_wait<3>();
        else if (r == 5) cp_wait<2>();
        else if (r == 6) cp_wait<1>();
        else             cp_wait<0>();

        const float* slot = ring + (size_t)(warp * 2048 + (r & 3) * 512) + lane * 4;
        uint4 c4[4];
        #pragma unroll
        for (int q = 0; q < 4; q++)
            c4[q] = *reinterpret_cast<const uint4*>(slot + q * 128);

        if (r < 4) {
            #pragma unroll
            for (int q = 0; q < 4; q++)
                cp_async16(rbase + (r & 3) * 2048 + q * 512,
                           row0 + (size_t)(r + 4) * 2048 + q * 512);
            cp_commit();
        }

        float e[4];
        #pragma unroll
        for (int q = 0; q < 4; q++) {
            ull u0 = h2f2(c4[q].x), u1 = h2f2(c4[q].y);
            ull u2 = h2f2(c4[q].z), u3 = h2f2(c4[q].w);
            ull d = fma2(u0, vq[q][0], fma2(u1, vq[q][1],
                    fma2(u2, vq[q][2], fma2(u3, vq[q][3], 0ull))));
            float2 df = ull2f2(d);
            float bp = df.x + df.y;
            bp += __shfl_xor_sync(0xffffffffu, bp, 1);
            bp += __shfl_xor_sync(0xffffffffu, bp, 2);
            e[q] = __expf(bp);
        }
        float tot = e[0] + e[1] + e[2] + e[3];
        tot += __shfl_xor_sync(0xffffffffu, tot, 4);
        tot += __shfl_xor_sync(0xffffffffu, tot, 8);
        tot += __shfl_xor_sync(0xffffffffu, tot, 16);
        float inv = __fdividef(1.0f, tot);
        #pragma unroll
        for (int q = 0; q < 4; q++) {
            ull cq2 = dupf(e[q] * inv);
            ull u0 = h2f2(c4[q].x), u1 = h2f2(c4[q].y);
            ull u2 = h2f2(c4[q].z), u3 = h2f2(c4[q].w);
            sacc[q][0] = fma2(cq2, u0, sacc[q][0]);
            sacc[q][1] = fma2(cq2, u1, sacc[q][1]);
            sacc[q][2] = fma2(cq2, u2, sacc[q][2]);
            sacc[q][3] = fma2(cq2, u3, sacc[q][3]);
        }
    }

    #pragma unroll
    for (int q = 0; q < 4; q++) {
        float2 f0 = ull2f2(sacc[q][0]), f1 = ull2f2(sacc[q][1]);
        float2 f2 = ull2f2(sacc[q][2]), f3 = ull2f2(sacc[q][3]);
        float* wp = ws + warp * 1024 + q * 256 + lane * 8;
        *reinterpret_cast<float4*>(wp)     = make_float4(f0.x, f0.y, f1.x, f1.y);
        *reinterpret_cast<float4*>(wp + 4) = make_float4(f2.x, f2.y, f3.x, f3.y);
    }
    __syncthreads();

    float4 a = *reinterpret_cast<const float4*>(ws + tid * 4);
    #pragma unroll
    for (int w2 = 1; w2 < 8; w2++) {
        float4 x = *reinterpret_cast<const float4*>(ws + w2 * 1024 + tid * 4);
        a.x += x.x; a.y += x.y; a.z += x.z; a.w += x.w;
    }
    red4(sout + b * JK_ + tid * 4, a);
}

// ---------------- final squash ----------------
__global__ void __launch_bounds__(1024) k_squash_final(float* __restrict__ out) {
    const int b   = blockIdx.x;
    const int tid = threadIdx.x;
    float sv = g_sb[2][b * JK_ + tid];
    float sq = sv * sv;
    #pragma unroll
    for (int o = 16; o; o >>= 1) sq += __shfl_xor_sync(0xffffffffu, sq, o);
    out[b * JK_ + tid] = (sq / ((1.0f + sq) * sqrtf(sq + 1e-7f))) * sv;
}

extern "C" void kernel_launch(void* const* d_in, const int* in_sizes, int n_in,
                              void* d_out, int out_size) {
    const float* inp = (const float*)d_in[0];   // [64, 2048, 16]
    const float* W   = (const float*)d_in[1];   // [32, 2048, 32, 16]
    float* out = (float*)d_out;                 // [64, 32, 32]

    cudaFuncSetAttribute(k_uhat, cudaFuncAttributeMaxDynamicSharedMemorySize, 73728);
    cudaFuncSetAttribute(k_route, cudaFuncAttributeMaxDynamicSharedMemorySize, 102400);

    k_init<<<192, 1024>>>();                            // zero s0,s1,s2
    k_uhat<<<1184, 256, 71680>>>(inp, W);               // HMMA u_hat + s0 (paired)
    k_route<<<dim3(32, 64), 256, 102400>>>(0, 0, 1, 0); // V0 -> s1
    k_route<<<dim3(32, 64), 256, 102400>>>(0, 1, 2, 1); // V0+V1 -> s2
    k_squash_final<<<64, 1024>>>(out);
}